// round 16
// baseline (speedup 1.0000x reference)
#include <cuda_runtime.h>
#include <cstdint>

// Scratch (device globals — no allocations allowed)
__device__ float g_k1[2 * 441 * 64];   // [b*441+sp][c]
__device__ float g_v [2 * 441 * 64];   // [b*441+pos][ch]  (TRANSPOSED)
__device__ float g_xT[2 * 441 * 64];   // [b*441+sp][c]    (x transposed)
__device__ int   g_cnt_prep;           // prep-block arrivals (self-resetting)
__device__ int   g_cnt_main;           // main-block completions

#define N_PREP 175
#define N_MAIN 400

__device__ __forceinline__ void cpa4(uint32_t saddr, const void* gaddr) {
    asm volatile("cp.async.ca.shared.global [%0], [%1], 4;" :: "r"(saddr), "l"(gaddr));
}

// ---------------------------------------------------------------------------
// Fused kernel. grid = 575 x 512, dynamic SMEM 62.9KB (3 blocks/SM).
//  bids 0..174  : prep role (k1 conv1d / v 3x3 conv transposed / x transpose)
//                 -> fence -> arrive on g_cnt_prep -> exit
//  bids 175..574: main role. Front (cp.async w2 | w1 | position math) runs
//                 concurrently with prep; spin on g_cnt_prep before touching
//                 g_k1/g_v/g_xT; rest identical to R15 pipeline.
// All prep bids fit in wave 1 (capacity 444 >= 175), so the spin cannot
// deadlock; last main block resets counters for graph replay.
// ---------------------------------------------------------------------------
#define NT 512
#define NC 8
// offsets (floats)
#define OFF_W1   0       // 1250 (pad 1252)
#define OFF_KQ   1252    // 50 x 8
#define OFF_R1   1652    // 25 x 8  (1652*4 % 16 == 0)
#define OFF_W2   1852    // 441 x 25 (pad 11028)
#define OFF_ES   12880   // 127 x 8
#define OFF_VS   13896   // 25 x 68 (row pad 68 -> 272B, 16B aligned)
#define OFF_RED  15596   // 14 x 8
#define OFF_CS   15708   // 8
#define SMF      15716   // 62864 B

__global__ __launch_bounds__(NT, 3) void fused_kernel(
                            const float* __restrict__ x,
                            const float* __restrict__ wk,
                            const float* __restrict__ bk,
                            const float* __restrict__ w1,
                            const float* __restrict__ bng,
                            const float* __restrict__ bnb,
                            const float* __restrict__ bnm,
                            const float* __restrict__ bnv,
                            const float* __restrict__ w2,
                            const float* __restrict__ b2,
                            const float* __restrict__ wv,
                            const float* __restrict__ bv,
                            float* __restrict__ out) {
    extern __shared__ float sm[];
    int tid = threadIdx.x;
    int bidx = blockIdx.x;

    if (bidx < N_PREP) {
        // ================= PREP ROLE =================
        int e = bidx;
        if (e < 111) {
            // k1[b,d,c] = bk[d] + sum_t x[b,t,d] * wk[d, t + 220 - c]; 4 d's
            float* xs2 = sm;          // 4 x 128
            float* wks = sm + 512;    // 4 x 128
            int i = tid >> 7, r = tid & 127;
            int d = 4 * e + i;
            if (d < 441) {
                int b = r >> 6, tt = r & 63;
                xs2[i * 128 + r] = x[(b * 64 + tt) * 441 + d];
                if (r < 127) wks[i * 128 + r] = wk[d * 441 + 157 + r];
            }
            __syncthreads();
            if (d < 441) {
                int b = r >> 6, c = r & 63;
                const float* xb = xs2 + i * 128 + b * 64;
                const float* wb = wks + i * 128;
                float acc = bk[d];
#pragma unroll
                for (int tt = 0; tt < 64; tt++)
                    acc += xb[tt] * wb[tt + 63 - c];
                g_k1[(b * 441 + d) * 64 + c] = acc;
            }
        } else if (e < 143) {
            // depthwise 3x3 conv, pad 1; store TRANSPOSED
            int vblk = e - 111;
            int idl = tid >> 7, p0 = tid & 127;
            int id = 4 * vblk + idl;        // [0,128)
            int b = id >> 6, ch = id & 63;
            float w[9];
#pragma unroll
            for (int i = 0; i < 9; i++) w[i] = wv[ch * 9 + i];
            float bias = bv[ch];
            const float* xp = x + (b * 64 + ch) * 441;
            for (int p = p0; p < 441; p += 128) {
                int y = p / 21, xx = p - y * 21;
                float acc = bias;
#pragma unroll
                for (int dy = 0; dy < 3; dy++) {
                    int yy = y + dy - 1;
                    if (yy < 0 || yy >= 21) continue;
#pragma unroll
                    for (int dx = 0; dx < 3; dx++) {
                        int xx2 = xx + dx - 1;
                        if (xx2 < 0 || xx2 >= 21) continue;
                        acc += xp[yy * 21 + xx2] * w[dy * 3 + dx];
                    }
                }
                g_v[(b * 441 + p) * 64 + ch] = acc;
            }
        } else {
            // x transpose: g_xT[(b*441+sp)*64+c] = x[(b*64+c)*441+sp]
            int tblk = e - 143;
            int idl = tid >> 7, p0 = tid & 127;
            int id = 4 * tblk + idl;        // [0,128)
            int b = id >> 6, c = id & 63;
            const float* xp = x + (b * 64 + c) * 441;
            for (int p = p0; p < 441; p += 128)
                g_xT[(b * 441 + p) * 64 + c] = xp[p];
        }
        // publish: make all this block's stores visible, then arrive
        __threadfence();
        __syncthreads();
        if (tid == 0) atomicAdd(&g_cnt_prep, 1);
        return;
    }

    // ================= MAIN ROLE =================
    float* w1s  = sm + OFF_W1;
    float* kqs  = sm + OFF_KQ;
    float* r1   = sm + OFF_R1;
    float* w2s  = sm + OFF_W2;
    float* es   = sm + OFF_ES;
    float* vs   = sm + OFF_VS;
    float* red  = sm + OFF_RED;
    float* csum = sm + OFF_CS;

    int bid  = bidx - N_PREP;
    int b    = bid / 200;
    int rem  = bid - b * 200;
    int g    = rem >> 3;
    int q    = rem & 7;
    int cbase = q * NC;
    int ph = g / 5, pw = g - ph * 5;

    // ---- front (independent of prep): async-stage w2[g] (43KB) ----
    {
        const float* src = w2 + g * 11025;
        uint32_t sbase = (uint32_t)__cvta_generic_to_shared(w2s);
        for (int i = tid; i < 11025; i += NT)
            cpa4(sbase + 4u * i, src + i);
        asm volatile("cp.async.commit_group;");
    }

    // position grids as arithmetic sequences
    int h0 = (ph < 2) ? ph + 5 : ph;
    int w0 = (pw < 2) ? pw + 5 : pw;
    int nh = (23 - h0 + 4) / 5;   // ceil
    int nw = (23 - w0 + 4) / 5;
    int npos = nh * nw;

    // load w1[g]
    for (int i = tid; i < 1250; i += NT) w1s[i] = w1[g * 1250 + i];

    // ---- wait for all prep blocks before touching g_k1/g_v/g_xT ----
    if (tid == 0) {
        while (*((volatile int*)&g_cnt_prep) < N_PREP) __nanosleep(64);
        __threadfence();
    }
    __syncthreads();

    // stage value vectors vs[p][t] via float4 (g_v is channel-contiguous)
    if (tid < npos * 16) {
        int p = tid >> 4, t4 = tid & 15;
        int pi = p / nw;
        int h = h0 + 5 * pi, w = w0 + 5 * (p - pi * nw);
        float4 v4 = {0.f, 0.f, 0.f, 0.f};
        if (h >= 4 && w >= 4)
            v4 = *(const float4*)&g_v[((b * 441) + (h - 4) * 21 + (w - 4)) * 64 + t4 * 4];
        *(float4*)&vs[p * 68 + t4 * 4] = v4;
    }

    // gather kq[i2][cl] (50 x 8): u = i2*64 + (cbase+cl) -> (s, c, ij)
    if (tid < 400) {
        int i2 = tid >> 3, cl = tid & 7;
        int u = i2 * 64 + cbase + cl;
        int s = u / 1600; int rm = u - s * 1600;
        int c = rm / 25;  int ij = rm - c * 25;
        int i5 = ij / 5, j5 = ij - i5 * 5;
        int row = 5 * i5 + ph, col = 5 * j5 + pw;
        float v = 0.f;
        if (row < 21 && col < 21) {
            int sp = row * 21 + col;
            const float* srcp = (s == 0) ? g_xT : g_k1;
            v = srcp[(b * 441 + sp) * 64 + c];
        }
        kqs[tid] = v;
    }
    __syncthreads();

    // ---- att1 (25 x 8), BN + ReLU ----
    if (tid < 200) {
        int o = tid >> 3, cl = tid & 7;
        float acc = 0.f;
#pragma unroll
        for (int i = 0; i < 50; i++) acc += w1s[o * 50 + i] * kqs[i * NC + cl];
        int go = g * 25 + o;
        float inv = bng[go] * rsqrtf(bnv[go] + 1e-5f);
        acc = (acc - bnm[go]) * inv + bnb[go];
        r1[tid] = fmaxf(acc, 0.f);
    }
    asm volatile("cp.async.wait_group 0;" ::: "memory");
    __syncthreads();

    // ---- logits + exp + partial sums: 2 d-rows x 4 cols per thread ----
    const float* b2g = b2 + g * 441;
    if (tid < 448) {
        int dg = tid >> 1, cg = tid & 1;
        int d0 = 2 * dg;
        float4 A0 = {0,0,0,0}, A1 = {0,0,0,0};
        if (d0 < 441) {
            int rb = (d0 + 1 < 441) ? (d0 + 1) * 25 : d0 * 25;
            int ra = d0 * 25;
#pragma unroll 5
            for (int o = 0; o < 25; o++) {
                float4 r = *(const float4*)&r1[o * NC + cg * 4];
                float v0 = w2s[ra + o];
                float v1 = w2s[rb + o];
                A0.x += v0*r.x; A0.y += v0*r.y; A0.z += v0*r.z; A0.w += v0*r.w;
                A1.x += v1*r.x; A1.y += v1*r.y; A1.z += v1*r.z; A1.w += v1*r.w;
            }
        }
        float s0 = 0.f, s1 = 0.f, s2 = 0.f, s3 = 0.f;
#define DO_ROW(Ai, di)                                                        \
        if ((di) < 441) {                                                     \
            float bb = b2g[di];                                               \
            float ex = __expf(Ai.x + bb), ey = __expf(Ai.y + bb);             \
            float ez = __expf(Ai.z + bb), ew = __expf(Ai.w + bb);             \
            s0 += ex; s1 += ey; s2 += ez; s3 += ew;                           \
            if ((di) >= 157 && (di) < 284) {                                  \
                float4 e4 = {ex, ey, ez, ew};                                 \
                *(float4*)&es[((di) - 157) * NC + cg * 4] = e4;               \
            }                                                                 \
        }
        DO_ROW(A0, d0)
        DO_ROW(A1, d0 + 1)
#undef DO_ROW
        // reduce over the 16 dg's per warp (flip lane bits 1..4)
#pragma unroll
        for (int off = 2; off <= 16; off <<= 1) {
            s0 += __shfl_xor_sync(0xFFFFFFFFu, s0, off);
            s1 += __shfl_xor_sync(0xFFFFFFFFu, s1, off);
            s2 += __shfl_xor_sync(0xFFFFFFFFu, s2, off);
            s3 += __shfl_xor_sync(0xFFFFFFFFu, s3, off);
        }
        int lane = tid & 31, wrp = tid >> 5;
        if (lane < 2) {
            float4 o4 = {s0, s1, s2, s3};
            *(float4*)&red[wrp * NC + lane * 4] = o4;   // cols lane*4..+3
        }
    }
    __syncthreads();

    if (tid < NC) {
        float s = 0.f;
#pragma unroll
        for (int w = 0; w < 14; w++) s += red[w * NC + tid];
        csum[tid] = 1.f / s;
    }
    __syncthreads();

    // ---- final dot: vs via LDS.128, es scalar ----
    if (tid < npos * NC) {
        int p = tid >> 3, c4 = tid & 7;
        int pi = p / nw;
        int h = h0 + 5 * pi, w = w0 + 5 * (p - pi * nw);
        int c = cbase + c4;
        float acc = 0.f;
        if (h >= 4 && w >= 4) {
            const float* vp = vs + p * 68;
            const float* lp = es + (63 - c) * NC + c4;   // d=220-c+t -> row 63-c+t
#pragma unroll
            for (int t4 = 0; t4 < 16; t4++) {
                float4 v4 = *(const float4*)&vp[t4 * 4];
                const float* l = lp + t4 * 32;
                acc += v4.x * l[0] + v4.y * l[8] + v4.z * l[16] + v4.w * l[24];
            }
        }
        acc *= csum[c4];
        if (h < 21 && w < 21) acc += g_k1[(b * 441 + h * 21 + w) * 64 + c];
        out[((b * 64 + c) * 21 + (h - 2)) * 21 + (w - 2)] = acc;
    }
    __syncthreads();

    // replay hygiene: last main block resets the counters (all main blocks
    // have passed their spin before the 400th increment can occur)
    if (tid == 0) {
        int d = atomicAdd(&g_cnt_main, 1);
        if (d == N_MAIN - 1) {
            g_cnt_prep = 0;
            g_cnt_main = 0;
            __threadfence();
        }
    }
}

extern "C" void kernel_launch(void* const* d_in, const int* in_sizes, int n_in,
                              void* d_out, int out_size) {
    const float* x   = (const float*)d_in[0];
    const float* wk  = (const float*)d_in[1];
    const float* bk  = (const float*)d_in[2];
    const float* w1  = (const float*)d_in[3];
    const float* bng = (const float*)d_in[4];
    const float* bnb = (const float*)d_in[5];
    const float* bnm = (const float*)d_in[6];
    const float* bnv = (const float*)d_in[7];
    const float* w2  = (const float*)d_in[8];
    const float* b2  = (const float*)d_in[9];
    const float* wv  = (const float*)d_in[10];
    const float* bv  = (const float*)d_in[11];
    float* out = (float*)d_out;

    cudaFuncSetAttribute(fused_kernel, cudaFuncAttributeMaxDynamicSharedMemorySize,
                         SMF * (int)sizeof(float));

    fused_kernel<<<N_PREP + N_MAIN, NT, SMF * (int)sizeof(float)>>>(
        x, wk, bk, w1, bng, bnb, bnm, bnv, w2, b2, wv, bv, out);
}

// round 17
// speedup vs baseline: 1.1597x; 1.1597x over previous
#include <cuda_runtime.h>
#include <cstdint>

// Scratch (device globals — no allocations allowed)
__device__ float g_k1[2 * 441 * 64];   // [b*441+sp][c]
__device__ float g_v [2 * 441 * 64];   // [b*441+pos][ch]  (TRANSPOSED)
__device__ float g_xT[2 * 441 * 64];   // [b*441+sp][c]    (x transposed)

__device__ __forceinline__ void cpa4(uint32_t saddr, const void* gaddr) {
    asm volatile("cp.async.ca.shared.global [%0], [%1], 4;" :: "r"(saddr), "l"(gaddr));
}
__device__ __forceinline__ void cpa16(uint32_t saddr, const void* gaddr) {
    asm volatile("cp.async.cg.shared.global [%0], [%1], 16;" :: "r"(saddr), "l"(gaddr));
}

// ---------------------------------------------------------------------------
// Kernel 1: k1 depthwise conv1d (4 d's/block), depthwise 3x3 conv (4 ch/block,
// transposed store), x transpose (4 ch/block).
// grid = 111 + 32 + 32 = 175 blocks x 512 threads. PDL trigger at entry.
// ---------------------------------------------------------------------------
__global__ __launch_bounds__(512) void prep_kernel(
                            const float* __restrict__ x,
                            const float* __restrict__ wk,
                            const float* __restrict__ bk,
                            const float* __restrict__ wv,
                            const float* __restrict__ bv) {
    asm volatile("griddepcontrol.launch_dependents;");
    int e = blockIdx.x;
    int tid = threadIdx.x;
    if (e < 111) {
        // k1[b,d,c] = bk[d] + sum_t x[b,t,d] * wk[d, t + 220 - c]; 4 d's
        __shared__ float xs2[4][128];   // [i][b*64+t]
        __shared__ float wks[4][128];   // [i][wk[d,157..283]]
        int i = tid >> 7, r = tid & 127;
        int d = 4 * e + i;
        if (d < 441) {
            int b = r >> 6, tt = r & 63;
            xs2[i][r] = x[(b * 64 + tt) * 441 + d];
            if (r < 127) wks[i][r] = wk[d * 441 + 157 + r];
        }
        __syncthreads();
        if (d < 441) {
            int b = r >> 6, c = r & 63;
            const float* xb = xs2[i] + b * 64;
            const float* wb = wks[i];
            float acc = bk[d];
#pragma unroll
            for (int tt = 0; tt < 64; tt++)
                acc += xb[tt] * wb[tt + 63 - c];
            g_k1[(b * 441 + d) * 64 + c] = acc;
        }
    } else if (e < 143) {
        // depthwise 3x3 conv, pad 1; store TRANSPOSED: g_v[(b*441+p)*64+ch]
        int vblk = e - 111;
        int idl = tid >> 7, p0 = tid & 127;
        int id = 4 * vblk + idl;        // [0,128)
        int b = id >> 6, ch = id & 63;
        float w[9];
#pragma unroll
        for (int i = 0; i < 9; i++) w[i] = wv[ch * 9 + i];
        float bias = bv[ch];
        const float* xp = x + (b * 64 + ch) * 441;
        for (int p = p0; p < 441; p += 128) {
            int y = p / 21, xx = p - y * 21;
            float acc = bias;
#pragma unroll
            for (int dy = 0; dy < 3; dy++) {
                int yy = y + dy - 1;
                if (yy < 0 || yy >= 21) continue;
#pragma unroll
                for (int dx = 0; dx < 3; dx++) {
                    int xx2 = xx + dx - 1;
                    if (xx2 < 0 || xx2 >= 21) continue;
                    acc += xp[yy * 21 + xx2] * w[dy * 3 + dx];
                }
            }
            g_v[(b * 441 + p) * 64 + ch] = acc;
        }
    } else {
        // x transpose: g_xT[(b*441+sp)*64+c] = x[(b*64+c)*441+sp]; 4 planes
        int tblk = e - 143;
        int idl = tid >> 7, p0 = tid & 127;
        int id = 4 * tblk + idl;        // [0,128)
        int b = id >> 6, c = id & 63;
        const float* xp = x + (b * 64 + c) * 441;
        for (int p = p0; p < 441; p += 128)
            g_xT[(b * 441 + p) * 64 + c] = xp[p];
    }
}

// ---------------------------------------------------------------------------
// Kernel 2: per (b, g, c-eighth of 8): fully block-local pipeline.
//   P0: cp.async(16B) w2 | w1 | vs(float4) | gather(coalesced)
//   -> att1 -> logits+exp+sums -> dot (vs via LDS.128)
// grid = 400 x 512, dynamic SMEM ~62.9KB, 3 blocks/SM.
// ---------------------------------------------------------------------------
#define NT 512
#define NC 8
// offsets (floats)
#define OFF_W1   0       // 1250 (pad 1252)
#define OFF_KQ   1252    // 50 x 8
#define OFF_R1   1652    // 25 x 8  (1652*4 % 16 == 0)
#define OFF_W2   1852    // 441 x 25 + shift pad (11032); 1852*4 % 16 == 0
#define OFF_ES   12884   // 127 x 8 (12884*4 % 16 == 0)
#define OFF_VS   13900   // 25 x 68 (13900*4 % 16 == 0)
#define OFF_RED  15600   // 14 x 8
#define OFF_CS   15712   // 8
#define SMF      15720   // 62880 B

__global__ __launch_bounds__(NT, 3) void main_kernel(
                            const float* __restrict__ x,
                            const float* __restrict__ w1,
                            const float* __restrict__ bng,
                            const float* __restrict__ bnb,
                            const float* __restrict__ bnm,
                            const float* __restrict__ bnv,
                            const float* __restrict__ w2,
                            const float* __restrict__ b2,
                            float* __restrict__ out) {
    extern __shared__ float sm[];
    float* w1s  = sm + OFF_W1;
    float* kqs  = sm + OFF_KQ;
    float* r1   = sm + OFF_R1;
    float* es   = sm + OFF_ES;
    float* vs   = sm + OFF_VS;
    float* red  = sm + OFF_RED;
    float* csum = sm + OFF_CS;

    int bid  = blockIdx.x;
    int b    = bid / 200;
    int rem  = bid - b * 200;
    int g    = rem >> 3;
    int q    = rem & 7;
    int cbase = q * NC;
    int ph = g / 5, pw = g - ph * 5;
    int tid = threadIdx.x;

    // ---- P0: async-stage w2[g] (43KB) with 16B cp.async + alignment shift ----
    int shift = (g * 11025) & 3;                 // = g mod 4
    float* w2s = sm + OFF_W2 + shift;            // logical base of w2[g]
    {
        const float* base = w2 + g * 11025 - shift;   // 16B-aligned
        int nv  = 11025 + shift;
        int nv4 = nv >> 2;
        uint32_t sbase = (uint32_t)__cvta_generic_to_shared(sm + OFF_W2);
        for (int i = tid; i < nv4; i += NT)
            cpa16(sbase + 16u * i, base + 4 * i);
        int tl = nv & 3;
        if (tid < tl)
            cpa4(sbase + 4u * (4 * nv4 + tid), base + 4 * nv4 + tid);
        asm volatile("cp.async.commit_group;");
    }

    // position grids as arithmetic sequences
    int h0 = (ph < 2) ? ph + 5 : ph;
    int w0 = (pw < 2) ? pw + 5 : pw;
    int nh = (23 - h0 + 4) / 5;   // ceil
    int nw = (23 - w0 + 4) / 5;
    int npos = nh * nw;

    // load w1[g]
    for (int i = tid; i < 1250; i += NT) w1s[i] = w1[g * 1250 + i];

    // ---- wait for prep's g_k1 / g_v / g_xT before reading them ----
    asm volatile("griddepcontrol.wait;" ::: "memory");

    // stage value vectors vs[p][t] via float4 (g_v is channel-contiguous)
    if (tid < npos * 16) {
        int p = tid >> 4, t4 = tid & 15;
        int pi = p / nw;
        int h = h0 + 5 * pi, w = w0 + 5 * (p - pi * nw);
        float4 v4 = {0.f, 0.f, 0.f, 0.f};
        if (h >= 4 && w >= 4)
            v4 = *(const float4*)&g_v[((b * 441) + (h - 4) * 21 + (w - 4)) * 64 + t4 * 4];
        *(float4*)&vs[p * 68 + t4 * 4] = v4;
    }

    // gather kq[i2][cl] (50 x 8): u = i2*64 + (cbase+cl) -> (s, c, ij)
    if (tid < 400) {
        int i2 = tid >> 3, cl = tid & 7;
        int u = i2 * 64 + cbase + cl;
        int s = u / 1600; int rm = u - s * 1600;
        int c = rm / 25;  int ij = rm - c * 25;
        int i5 = ij / 5, j5 = ij - i5 * 5;
        int row = 5 * i5 + ph, col = 5 * j5 + pw;
        float v = 0.f;
        if (row < 21 && col < 21) {
            int sp = row * 21 + col;
            const float* srcp = (s == 0) ? g_xT : g_k1;
            v = srcp[(b * 441 + sp) * 64 + c];
        }
        kqs[tid] = v;
    }
    __syncthreads();

    // ---- att1 (25 x 8), BN + ReLU ----
    if (tid < 200) {
        int o = tid >> 3, cl = tid & 7;
        float acc = 0.f;
#pragma unroll
        for (int i = 0; i < 50; i++) acc += w1s[o * 50 + i] * kqs[i * NC + cl];
        int go = g * 25 + o;
        float inv = bng[go] * rsqrtf(bnv[go] + 1e-5f);
        acc = (acc - bnm[go]) * inv + bnb[go];
        r1[tid] = fmaxf(acc, 0.f);
    }
    asm volatile("cp.async.wait_group 0;" ::: "memory");
    __syncthreads();

    // ---- logits + exp + partial sums: 2 d-rows x 4 cols per thread ----
    const float* b2g = b2 + g * 441;
    if (tid < 448) {
        int dg = tid >> 1, cg = tid & 1;
        int d0 = 2 * dg;
        float4 A0 = {0,0,0,0}, A1 = {0,0,0,0};
        if (d0 < 441) {
            int rb = (d0 + 1 < 441) ? (d0 + 1) * 25 : d0 * 25;
            int ra = d0 * 25;
#pragma unroll 5
            for (int o = 0; o < 25; o++) {
                float4 r = *(const float4*)&r1[o * NC + cg * 4];
                float v0 = w2s[ra + o];
                float v1 = w2s[rb + o];
                A0.x += v0*r.x; A0.y += v0*r.y; A0.z += v0*r.z; A0.w += v0*r.w;
                A1.x += v1*r.x; A1.y += v1*r.y; A1.z += v1*r.z; A1.w += v1*r.w;
            }
        }
        float s0 = 0.f, s1 = 0.f, s2 = 0.f, s3 = 0.f;
#define DO_ROW(Ai, di)                                                        \
        if ((di) < 441) {                                                     \
            float bb = b2g[di];                                               \
            float ex = __expf(Ai.x + bb), ey = __expf(Ai.y + bb);             \
            float ez = __expf(Ai.z + bb), ew = __expf(Ai.w + bb);             \
            s0 += ex; s1 += ey; s2 += ez; s3 += ew;                           \
            if ((di) >= 157 && (di) < 284) {                                  \
                float4 e4 = {ex, ey, ez, ew};                                 \
                *(float4*)&es[((di) - 157) * NC + cg * 4] = e4;               \
            }                                                                 \
        }
        DO_ROW(A0, d0)
        DO_ROW(A1, d0 + 1)
#undef DO_ROW
        // reduce over the 16 dg's per warp (flip lane bits 1..4)
#pragma unroll
        for (int off = 2; off <= 16; off <<= 1) {
            s0 += __shfl_xor_sync(0xFFFFFFFFu, s0, off);
            s1 += __shfl_xor_sync(0xFFFFFFFFu, s1, off);
            s2 += __shfl_xor_sync(0xFFFFFFFFu, s2, off);
            s3 += __shfl_xor_sync(0xFFFFFFFFu, s3, off);
        }
        int lane = tid & 31, wrp = tid >> 5;
        if (lane < 2) {
            float4 o4 = {s0, s1, s2, s3};
            *(float4*)&red[wrp * NC + lane * 4] = o4;   // cols lane*4..+3
        }
    }
    __syncthreads();

    if (tid < NC) {
        float s = 0.f;
#pragma unroll
        for (int w = 0; w < 14; w++) s += red[w * NC + tid];
        csum[tid] = 1.f / s;
    }
    __syncthreads();

    // ---- final dot: vs via LDS.128, es scalar ----
    if (tid < npos * NC) {
        int p = tid >> 3, c4 = tid & 7;
        int pi = p / nw;
        int h = h0 + 5 * pi, w = w0 + 5 * (p - pi * nw);
        int c = cbase + c4;
        float acc = 0.f;
        if (h >= 4 && w >= 4) {
            const float* vp = vs + p * 68;
            const float* lp = es + (63 - c) * NC + c4;   // d=220-c+t -> row 63-c+t
#pragma unroll
            for (int t4 = 0; t4 < 16; t4++) {
                float4 v4 = *(const float4*)&vp[t4 * 4];
                const float* l = lp + t4 * 32;
                acc += v4.x * l[0] + v4.y * l[8] + v4.z * l[16] + v4.w * l[24];
            }
        }
        acc *= csum[c4];
        if (h < 21 && w < 21) acc += g_k1[(b * 441 + h * 21 + w) * 64 + c];
        out[((b * 64 + c) * 21 + (h - 2)) * 21 + (w - 2)] = acc;
    }
}

extern "C" void kernel_launch(void* const* d_in, const int* in_sizes, int n_in,
                              void* d_out, int out_size) {
    const float* x   = (const float*)d_in[0];
    const float* wk  = (const float*)d_in[1];
    const float* bk  = (const float*)d_in[2];
    const float* w1  = (const float*)d_in[3];
    const float* bng = (const float*)d_in[4];
    const float* bnb = (const float*)d_in[5];
    const float* bnm = (const float*)d_in[6];
    const float* bnv = (const float*)d_in[7];
    const float* w2  = (const float*)d_in[8];
    const float* b2  = (const float*)d_in[9];
    const float* wv  = (const float*)d_in[10];
    const float* bv  = (const float*)d_in[11];
    float* out = (float*)d_out;

    cudaFuncSetAttribute(main_kernel, cudaFuncAttributeMaxDynamicSharedMemorySize,
                         SMF * (int)sizeof(float));

    prep_kernel<<<175, 512>>>(x, wk, bk, wv, bv);

    // PDL launch (deterministic fallback to plain launch if rejected)
    cudaLaunchConfig_t cfg = {};
    cfg.gridDim = dim3(400, 1, 1);
    cfg.blockDim = dim3(NT, 1, 1);
    cfg.dynamicSmemBytes = SMF * sizeof(float);
    cfg.stream = 0;
    cudaLaunchAttribute attrs[1];
    attrs[0].id = cudaLaunchAttributeProgrammaticStreamSerialization;
    attrs[0].val.programmaticStreamSerializationAllowed = 1;
    cfg.attrs = attrs;
    cfg.numAttrs = 1;
    cudaError_t err = cudaLaunchKernelEx(&cfg, main_kernel,
                                         x, w1, bng, bnb, bnm, bnv, w2, b2, out);
    if (err != cudaSuccess) {
        (void)cudaGetLastError();
        main_kernel<<<400, NT, SMF * sizeof(float)>>>(
            x, w1, bng, bnb, bnm, bnv, w2, b2, out);
    }
}